// round 1
// baseline (speedup 1.0000x reference)
#include <cuda_runtime.h>
#include <math.h>

#define DIMX  1024
#define NH    16
#define DH    64
#define LSEQ  2048
#define NB    2
#define INNER 1024
#define QK_SCALE 0.125f

// Scratch (allocation-free rule: __device__ globals)
__device__ float g_q[(size_t)NB*NH*LSEQ*DH];   // [b,h,l,dh]
__device__ float g_k[(size_t)NB*NH*LSEQ*DH];
__device__ float g_v[(size_t)NB*NH*LSEQ*DH];
__device__ float g_z[(size_t)NB*LSEQ*INNER];   // [b,l,h*dh]

// ---------------------------------------------------------------------------
// Kernel 1: QKV GEMM  C[m,n] = x[m,:] @ W_qkv[:,n], m=4096, n=3072, k=1024
// 128x128 tiles, BK=8, 256 threads, 8x8 micro-tile. Epilogue scatters to
// q/k/v in [b,h,l,dh] layout.
// ---------------------------------------------------------------------------
__global__ __launch_bounds__(256) void qkv_gemm(const float* __restrict__ x,
                                                const float* __restrict__ W)
{
    __shared__ float As[8][128];   // transposed: As[k][m]
    __shared__ float Bs[8][128];   // Bs[k][n]
    const int tid = threadIdx.x;
    const int tx = tid & 15, ty = tid >> 4;
    const int m0 = blockIdx.y * 128, n0 = blockIdx.x * 128;

    const int arow = tid >> 1, acol = (tid & 1) * 4;
    const int brow = tid >> 5, bcol = (tid & 31) * 4;

    float c[8][8];
    #pragma unroll
    for (int i = 0; i < 8; i++)
        #pragma unroll
        for (int j = 0; j < 8; j++) c[i][j] = 0.f;

    for (int kt = 0; kt < 1024; kt += 8) {
        float4 av = *(const float4*)&x[(size_t)(m0 + arow) * 1024 + kt + acol];
        float4 bv = *(const float4*)&W[(size_t)(kt + brow) * 3072 + n0 + bcol];
        __syncthreads();
        As[acol + 0][arow] = av.x;
        As[acol + 1][arow] = av.y;
        As[acol + 2][arow] = av.z;
        As[acol + 3][arow] = av.w;
        *(float4*)&Bs[brow][bcol] = bv;
        __syncthreads();
        #pragma unroll
        for (int k = 0; k < 8; k++) {
            float4 a0 = *(const float4*)&As[k][ty * 8];
            float4 a1 = *(const float4*)&As[k][ty * 8 + 4];
            float4 b0 = *(const float4*)&Bs[k][tx * 8];
            float4 b1 = *(const float4*)&Bs[k][tx * 8 + 4];
            float fa[8] = {a0.x, a0.y, a0.z, a0.w, a1.x, a1.y, a1.z, a1.w};
            float fb[8] = {b0.x, b0.y, b0.z, b0.w, b1.x, b1.y, b1.z, b1.w};
            #pragma unroll
            for (int i = 0; i < 8; i++)
                #pragma unroll
                for (int j = 0; j < 8; j++)
                    c[i][j] = fmaf(fa[i], fb[j], c[i][j]);
        }
    }

    // Scatter epilogue into q/k/v [b,h,l,dh]
    #pragma unroll
    for (int i = 0; i < 8; i++) {
        int m = m0 + ty * 8 + i;
        int bb = m >> 11;          // /2048
        int ll = m & 2047;
        #pragma unroll
        for (int j = 0; j < 8; j++) {
            int n = n0 + tx * 8 + j;
            int three = n >> 10;
            int rem = n & 1023;
            int hh = rem >> 6;
            int dd = rem & 63;
            size_t dst = (((size_t)(bb * NH + hh) * LSEQ) + ll) * DH + dd;
            float* base = (three == 0) ? g_q : (three == 1) ? g_k : g_v;
            base[dst] = c[i][j];
        }
    }
}

// ---------------------------------------------------------------------------
// Kernel 2: fused flash attention with softmax-first + multiplicative mask +
// renormalization. attn_final = e*mask / (sum(e*mask) + eps*Z).
// BM=BN=64, 256 threads (16x16), each 4x4 micro-tile.
// ---------------------------------------------------------------------------
__global__ __launch_bounds__(256) void attn_kernel(const float* __restrict__ mask,
                                                   float* __restrict__ z)
{
    extern __shared__ float sm[];
    float* Qs = sm;                    // [64][65]
    float* Ks = Qs + 64 * 65;          // [64][65]
    float* Ss = Ks + 64 * 65;          // [64][65] (S tile, then P*mask in place)
    float* Vs = Ss + 64 * 65;          // [64][64]
    float* Ms = Vs + 64 * 64;          // [64][64] mask tile
    float* row_m  = Ms + 64 * 64;      // [64]
    float* row_sa = row_m + 64;        // [64] sum exp (Z)
    float* row_sk = row_sa + 64;       // [64] sum exp*mask
    float* row_sc = row_sk + 64;       // [64] rescale factor

    const int tid = threadIdx.x;
    const int tx = tid & 15, ty = tid >> 4;
    const int qb = blockIdx.x;         // 0..31 query row-block
    const int bh = blockIdx.y;         // 0..31 (b*h)
    const int bb = bh >> 4, hh = bh & 15;
    const int q0 = qb * 64;

    const float* qbase = g_q + ((size_t)bh * LSEQ + q0) * DH;
    const float* kbase = g_k + (size_t)bh * LSEQ * DH;
    const float* vbase = g_v + (size_t)bh * LSEQ * DH;

    // Load Q tile [64][64] -> padded shared
    #pragma unroll
    for (int p = 0; p < 4; p++) {
        int r = p * 16 + (tid >> 4);
        int d = (tid & 15) * 4;
        float4 v4 = *(const float4*)&qbase[r * 64 + d];
        Qs[r * 65 + d + 0] = v4.x;
        Qs[r * 65 + d + 1] = v4.y;
        Qs[r * 65 + d + 2] = v4.z;
        Qs[r * 65 + d + 3] = v4.w;
    }
    if (tid < 64) {
        row_m[tid]  = -1e30f;
        row_sa[tid] = 0.f;
        row_sk[tid] = 0.f;
    }

    float acc[4][4];
    #pragma unroll
    for (int i = 0; i < 4; i++)
        #pragma unroll
        for (int j = 0; j < 4; j++) acc[i][j] = 0.f;

    for (int jt = 0; jt < LSEQ / 64; jt++) {
        __syncthreads();  // prior iteration done with Ks/Vs/Ms
        // Load K, V, mask tiles
        #pragma unroll
        for (int p = 0; p < 4; p++) {
            int r = p * 16 + (tid >> 4);
            int d = (tid & 15) * 4;
            float4 kv = *(const float4*)&kbase[(jt * 64 + r) * 64 + d];
            Ks[r * 65 + d + 0] = kv.x;
            Ks[r * 65 + d + 1] = kv.y;
            Ks[r * 65 + d + 2] = kv.z;
            Ks[r * 65 + d + 3] = kv.w;
            float4 vv = *(const float4*)&vbase[(jt * 64 + r) * 64 + d];
            *(float4*)&Vs[r * 64 + d] = vv;
            float4 mv = *(const float4*)&mask[((size_t)bb * LSEQ + q0 + r) * LSEQ + jt * 64 + d];
            *(float4*)&Ms[r * 64 + d] = mv;
        }
        __syncthreads();

        // S = Q K^T * scale
        float s[4][4];
        #pragma unroll
        for (int i = 0; i < 4; i++)
            #pragma unroll
            for (int j = 0; j < 4; j++) s[i][j] = 0.f;
        #pragma unroll 8
        for (int d = 0; d < 64; d++) {
            float fa[4], fb[4];
            #pragma unroll
            for (int i = 0; i < 4; i++) fa[i] = Qs[(ty * 4 + i) * 65 + d];
            #pragma unroll
            for (int j = 0; j < 4; j++) fb[j] = Ks[(tx * 4 + j) * 65 + d];
            #pragma unroll
            for (int i = 0; i < 4; i++)
                #pragma unroll
                for (int j = 0; j < 4; j++)
                    s[i][j] = fmaf(fa[i], fb[j], s[i][j]);
        }
        #pragma unroll
        for (int i = 0; i < 4; i++)
            #pragma unroll
            for (int j = 0; j < 4; j++)
                Ss[(ty * 4 + i) * 65 + tx * 4 + j] = s[i][j] * QK_SCALE;
        __syncthreads();

        // Online softmax per row (threads 0..63)
        if (tid < 64) {
            int r = tid;
            float mo = row_m[r];
            float mx = mo;
            #pragma unroll 8
            for (int cc = 0; cc < 64; cc++)
                mx = fmaxf(mx, Ss[r * 65 + cc]);
            float sc = __expf(mo - mx);
            float sa = row_sa[r] * sc;
            float sk = row_sk[r] * sc;
            #pragma unroll 8
            for (int cc = 0; cc < 64; cc++) {
                float p = __expf(Ss[r * 65 + cc] - mx);
                sa += p;
                float pm = p * Ms[r * 64 + cc];
                sk += pm;
                Ss[r * 65 + cc] = pm;   // P*mask in place
            }
            row_m[r] = mx;
            row_sa[r] = sa;
            row_sk[r] = sk;
            row_sc[r] = sc;
        }
        __syncthreads();

        // acc = acc*scale + (P*mask) @ V
        float rs[4];
        #pragma unroll
        for (int i = 0; i < 4; i++) rs[i] = row_sc[ty * 4 + i];
        #pragma unroll
        for (int i = 0; i < 4; i++)
            #pragma unroll
            for (int j = 0; j < 4; j++) acc[i][j] *= rs[i];
        #pragma unroll 8
        for (int cc = 0; cc < 64; cc++) {
            float fa[4];
            #pragma unroll
            for (int i = 0; i < 4; i++) fa[i] = Ss[(ty * 4 + i) * 65 + cc];
            float4 fb = *(const float4*)&Vs[cc * 64 + tx * 4];
            #pragma unroll
            for (int i = 0; i < 4; i++) {
                acc[i][0] = fmaf(fa[i], fb.x, acc[i][0]);
                acc[i][1] = fmaf(fa[i], fb.y, acc[i][1]);
                acc[i][2] = fmaf(fa[i], fb.z, acc[i][2]);
                acc[i][3] = fmaf(fa[i], fb.w, acc[i][3]);
            }
        }
    }

    // Final normalize: / (sum_mask + eps * Z), write z[b,l,h*dh]
    #pragma unroll
    for (int i = 0; i < 4; i++) {
        int r = ty * 4 + i;
        float den = row_sk[r] + 1e-10f * row_sa[r];
        float inv = 1.f / den;
        float4 o;
        o.x = acc[i][0] * inv;
        o.y = acc[i][1] * inv;
        o.z = acc[i][2] * inv;
        o.w = acc[i][3] * inv;
        *(float4*)&z[((size_t)bb * LSEQ + q0 + r) * INNER + hh * 64 + tx * 4] = o;
    }
}

// ---------------------------------------------------------------------------
// Kernel 3: out = z @ W_out + b_out, m=4096, n=1024, k=1024
// ---------------------------------------------------------------------------
__global__ __launch_bounds__(256) void out_gemm(const float* __restrict__ z,
                                                const float* __restrict__ W,
                                                const float* __restrict__ bias,
                                                float* __restrict__ out)
{
    __shared__ float As[8][128];
    __shared__ float Bs[8][128];
    const int tid = threadIdx.x;
    const int tx = tid & 15, ty = tid >> 4;
    const int m0 = blockIdx.y * 128, n0 = blockIdx.x * 128;

    const int arow = tid >> 1, acol = (tid & 1) * 4;
    const int brow = tid >> 5, bcol = (tid & 31) * 4;

    float c[8][8];
    #pragma unroll
    for (int i = 0; i < 8; i++)
        #pragma unroll
        for (int j = 0; j < 8; j++) c[i][j] = 0.f;

    for (int kt = 0; kt < 1024; kt += 8) {
        float4 av = *(const float4*)&z[(size_t)(m0 + arow) * 1024 + kt + acol];
        float4 bv = *(const float4*)&W[(size_t)(kt + brow) * 1024 + n0 + bcol];
        __syncthreads();
        As[acol + 0][arow] = av.x;
        As[acol + 1][arow] = av.y;
        As[acol + 2][arow] = av.z;
        As[acol + 3][arow] = av.w;
        *(float4*)&Bs[brow][bcol] = bv;
        __syncthreads();
        #pragma unroll
        for (int k = 0; k < 8; k++) {
            float4 a0 = *(const float4*)&As[k][ty * 8];
            float4 a1 = *(const float4*)&As[k][ty * 8 + 4];
            float4 b0 = *(const float4*)&Bs[k][tx * 8];
            float4 b1 = *(const float4*)&Bs[k][tx * 8 + 4];
            float fa[8] = {a0.x, a0.y, a0.z, a0.w, a1.x, a1.y, a1.z, a1.w};
            float fb[8] = {b0.x, b0.y, b0.z, b0.w, b1.x, b1.y, b1.z, b1.w};
            #pragma unroll
            for (int i = 0; i < 8; i++)
                #pragma unroll
                for (int j = 0; j < 8; j++)
                    c[i][j] = fmaf(fa[i], fb[j], c[i][j]);
        }
    }

    #pragma unroll
    for (int i = 0; i < 8; i++) {
        int m = m0 + ty * 8 + i;
        #pragma unroll
        for (int j = 0; j < 8; j += 4) {
            int n = n0 + tx * 8 + j;
            float4 o;
            o.x = c[i][j + 0] + bias[n + 0];
            o.y = c[i][j + 1] + bias[n + 1];
            o.z = c[i][j + 2] + bias[n + 2];
            o.w = c[i][j + 3] + bias[n + 3];
            *(float4*)&out[(size_t)m * 1024 + n] = o;
        }
    }
}

// ---------------------------------------------------------------------------
extern "C" void kernel_launch(void* const* d_in, const int* in_sizes, int n_in,
                              void* d_out, int out_size)
{
    const float* x     = (const float*)d_in[0];  // [2,2048,1024]
    const float* mask  = (const float*)d_in[1];  // [2,2048,2048]
    const float* W_qkv = (const float*)d_in[2];  // [1024,3072]
    const float* W_out = (const float*)d_in[3];  // [1024,1024]
    const float* b_out = (const float*)d_in[4];  // [1024]
    float* out = (float*)d_out;

    // z scratch pointer (device symbol address known at compile time via kernels;
    // pass via kernel args using the device-global directly in kernels)
    // QKV projection
    {
        dim3 grid(3072 / 128, 4096 / 128);
        qkv_gemm<<<grid, 256>>>(x, W_qkv);
    }
    // Attention
    {
        const int smem_bytes = (64 * 65 * 3 + 64 * 64 * 2 + 4 * 64) * sizeof(float);
        cudaFuncSetAttribute(attn_kernel, cudaFuncAttributeMaxDynamicSharedMemorySize,
                             smem_bytes);
        dim3 grid(LSEQ / 64, NB * NH);
        attn_kernel<<<grid, 256, smem_bytes>>>(mask, g_z);
    }
    // Output projection
    {
        dim3 grid(1024 / 128, 4096 / 128);
        out_gemm<<<grid, 256>>>(g_z, W_out, b_out, out);
    }
}

// round 3
// speedup vs baseline: 1.2888x; 1.2888x over previous
#include <cuda_runtime.h>
#include <cstdint>
#include <math.h>

#define NH    16
#define DH    64
#define LSEQ  2048
#define NB    2
#define INNER 1024
#define QK_SCALE 0.125f

// Scratch (__device__ globals; allocation-free rule)
__device__ float g_q[(size_t)NB*NH*LSEQ*DH];   // [b,h,l,dh]
__device__ float g_k[(size_t)NB*NH*LSEQ*DH];
__device__ float g_v[(size_t)NB*NH*LSEQ*DH];
__device__ float g_z[(size_t)NB*LSEQ*INNER];   // [b,l,h*dh]
__device__ float g_wqkvT[(size_t)3072*1024];   // W_qkv^T [n=3072][k=1024]
__device__ float g_woutT[(size_t)1024*1024];   // W_out^T [n=1024][k=1024]

// ---------------------------------------------------------------------------
// mma.sync m16n8k8 tf32 (sm_80+; works on plain sm_103 target)
// ---------------------------------------------------------------------------
__device__ __forceinline__ void mma8(float d[4], const uint32_t a[4],
                                     const uint32_t b[2]) {
    asm volatile(
        "mma.sync.aligned.m16n8k8.row.col.f32.tf32.tf32.f32 "
        "{%0,%1,%2,%3}, {%4,%5,%6,%7}, {%8,%9}, {%0,%1,%2,%3};"
        : "+f"(d[0]), "+f"(d[1]), "+f"(d[2]), "+f"(d[3])
        : "r"(a[0]), "r"(a[1]), "r"(a[2]), "r"(a[3]),
          "r"(b[0]), "r"(b[1]));
}
__device__ __forceinline__ uint32_t f2tf32(float f) {
    uint32_t o;
    asm("cvt.rna.tf32.f32 %0, %1;" : "=r"(o) : "f"(f));
    return o;
}

// ---------------------------------------------------------------------------
// Transpose: src [R][C] -> dst [C][R]
// ---------------------------------------------------------------------------
__global__ void transpose32(const float* __restrict__ src, float* __restrict__ dst,
                            int R, int C)
{
    __shared__ float t[32][33];
    int c0 = blockIdx.x * 32, r0 = blockIdx.y * 32;
    #pragma unroll
    for (int i = 0; i < 4; i++)
        t[threadIdx.y + i * 8][threadIdx.x] =
            src[(size_t)(r0 + threadIdx.y + i * 8) * C + c0 + threadIdx.x];
    __syncthreads();
    #pragma unroll
    for (int i = 0; i < 4; i++)
        dst[(size_t)(c0 + threadIdx.y + i * 8) * R + r0 + threadIdx.x] =
            t[threadIdx.x][threadIdx.y + i * 8];
}

// ---------------------------------------------------------------------------
// tf32 mma.sync GEMM: C[4096][Ntot] = A[4096][1024] @ Bt[Ntot][1024]^T
// 128x128 tile, BK=64, 256 threads = 8 warps (2m x 4n), warp tile 64x32.
// mode 0: scatter to q/k/v. mode 1: out = C + bias.
// ---------------------------------------------------------------------------
__global__ __launch_bounds__(256) void mma_gemm(const float* __restrict__ A,
                                                const float* __restrict__ Bt,
                                                const float* __restrict__ bias,
                                                float* __restrict__ outp,
                                                int mode)
{
    extern __shared__ uint32_t sh[];
    uint32_t* As = sh;              // [128][68] tf32 bits
    uint32_t* Bs = sh + 128 * 68;   // [128][68]

    const int tid  = threadIdx.x;
    const int lane = tid & 31;
    const int w    = tid >> 5;
    const int wm   = w >> 2;        // 0..1
    const int wn   = w & 3;         // 0..3
    const int g    = lane >> 2;
    const int t    = lane & 3;
    const int m0   = blockIdx.y * 128;
    const int n0   = blockIdx.x * 128;

    float acc[4][4][4];
    #pragma unroll
    for (int mi = 0; mi < 4; mi++)
        #pragma unroll
        for (int nj = 0; nj < 4; nj++)
            #pragma unroll
            for (int r = 0; r < 4; r++) acc[mi][nj][r] = 0.f;

    #pragma unroll 1
    for (int kt = 0; kt < 16; kt++) {
        __syncthreads();
        // Load 128x64 of A and Bt, cvt to tf32, store to smem
        #pragma unroll
        for (int i = 0; i < 8; i++) {
            int s = tid + 256 * i;
            int r = s >> 4, c = (s & 15) * 4;
            float4 a4 = *(const float4*)&A[(size_t)(m0 + r) * 1024 + kt * 64 + c];
            uint4 ta = { f2tf32(a4.x), f2tf32(a4.y), f2tf32(a4.z), f2tf32(a4.w) };
            *(uint4*)&As[r * 68 + c] = ta;
            float4 b4 = *(const float4*)&Bt[(size_t)(n0 + r) * 1024 + kt * 64 + c];
            uint4 tb = { f2tf32(b4.x), f2tf32(b4.y), f2tf32(b4.z), f2tf32(b4.w) };
            *(uint4*)&Bs[r * 68 + c] = tb;
        }
        __syncthreads();

        #pragma unroll
        for (int kk = 0; kk < 8; kk++) {
            uint32_t af[4][4], bf[4][2];
            #pragma unroll
            for (int mi = 0; mi < 4; mi++) {
                int rb = wm * 64 + mi * 16;
                af[mi][0] = As[(rb + g) * 68 + kk * 8 + t];
                af[mi][1] = As[(rb + g + 8) * 68 + kk * 8 + t];
                af[mi][2] = As[(rb + g) * 68 + kk * 8 + t + 4];
                af[mi][3] = As[(rb + g + 8) * 68 + kk * 8 + t + 4];
            }
            #pragma unroll
            for (int nj = 0; nj < 4; nj++) {
                int nb = wn * 32 + nj * 8;
                bf[nj][0] = Bs[(nb + g) * 68 + kk * 8 + t];
                bf[nj][1] = Bs[(nb + g) * 68 + kk * 8 + t + 4];
            }
            #pragma unroll
            for (int mi = 0; mi < 4; mi++)
                #pragma unroll
                for (int nj = 0; nj < 4; nj++)
                    mma8(acc[mi][nj], af[mi], bf[nj]);
        }
    }

    // Epilogue
    #pragma unroll
    for (int mi = 0; mi < 4; mi++) {
        int r_lo = m0 + wm * 64 + mi * 16 + g;
        int r_hi = r_lo + 8;
        #pragma unroll
        for (int nj = 0; nj < 4; nj++) {
            int n = n0 + wn * 32 + nj * 8 + 2 * t;
            if (mode == 1) {
                float2 o0 = { acc[mi][nj][0] + bias[n], acc[mi][nj][1] + bias[n + 1] };
                float2 o1 = { acc[mi][nj][2] + bias[n], acc[mi][nj][3] + bias[n + 1] };
                *(float2*)&outp[(size_t)r_lo * 1024 + n] = o0;
                *(float2*)&outp[(size_t)r_hi * 1024 + n] = o1;
            } else {
                int three = n >> 10, rem = n & 1023, hh = rem >> 6, dd = rem & 63;
                float* base = (three == 0) ? g_q : (three == 1) ? g_k : g_v;
                int bb_lo = r_lo >> 11, ll_lo = r_lo & 2047;
                int bb_hi = r_hi >> 11, ll_hi = r_hi & 2047;
                float2 o0 = { acc[mi][nj][0], acc[mi][nj][1] };
                float2 o1 = { acc[mi][nj][2], acc[mi][nj][3] };
                *(float2*)&base[(((size_t)(bb_lo * NH + hh) * LSEQ) + ll_lo) * DH + dd] = o0;
                *(float2*)&base[(((size_t)(bb_hi * NH + hh) * LSEQ) + ll_hi) * DH + dd] = o1;
            }
        }
    }
}

// ---------------------------------------------------------------------------
// Attention via mma.sync tf32: BM=64 q-rows, 128 threads (4 warps x 16 rows).
// No-max exact softmax: p = exp(s); sa = sum p; sk = sum p*mask;
// z = (p*mask) @ V / (sk + eps*sa). Q frags persistent in registers.
// ---------------------------------------------------------------------------
__global__ __launch_bounds__(128) void attn_mma(const float* __restrict__ mask,
                                                float* __restrict__ z)
{
    extern __shared__ uint32_t sh[];
    uint32_t* Ks = sh;                   // [64][68] tf32 bits
    uint32_t* Vs = Ks + 64 * 68;         // [64][72] tf32 bits
    uint32_t* Ps = Vs + 64 * 72;         // [64][68] tf32 bits (also Q staging)
    float*    Ms = (float*)(Ps + 64 * 68);  // [64][68] mask

    const int tid  = threadIdx.x;
    const int lane = tid & 31;
    const int w    = tid >> 5;           // 0..3
    const int g    = lane >> 2;
    const int t    = lane & 3;
    const int qb   = blockIdx.x;
    const int bh   = blockIdx.y;
    const int bb   = bh >> 4, hh = bh & 15;
    const int q0   = qb * 64;
    const int rw   = w * 16;             // warp's row offset within block

    const float* qp = g_q + ((size_t)bh * LSEQ + q0) * DH;
    const float* kp = g_k + (size_t)bh * LSEQ * DH;
    const float* vp = g_v + (size_t)bh * LSEQ * DH;

    // Stage Q tile (64x64) into Ps as raw floats
    #pragma unroll
    for (int i = 0; i < 8; i++) {
        int s = tid + 128 * i;
        int r = s >> 4, c = (s & 15) * 4;
        *(float4*)&Ps[r * 68 + c] = *(const float4*)&qp[r * 64 + c];
    }
    __syncthreads();

    // Build persistent Q fragments (scale folded in)
    uint32_t qa[8][4];
    {
        const float* Pf = (const float*)Ps;
        #pragma unroll
        for (int kk = 0; kk < 8; kk++) {
            qa[kk][0] = f2tf32(QK_SCALE * Pf[(rw + g) * 68 + kk * 8 + t]);
            qa[kk][1] = f2tf32(QK_SCALE * Pf[(rw + g + 8) * 68 + kk * 8 + t]);
            qa[kk][2] = f2tf32(QK_SCALE * Pf[(rw + g) * 68 + kk * 8 + t + 4]);
            qa[kk][3] = f2tf32(QK_SCALE * Pf[(rw + g + 8) * 68 + kk * 8 + t + 4]);
        }
    }

    float zacc[8][4];
    #pragma unroll
    for (int j = 0; j < 8; j++)
        #pragma unroll
        for (int r = 0; r < 4; r++) zacc[j][r] = 0.f;
    float sa_lo = 0.f, sa_hi = 0.f, sk_lo = 0.f, sk_hi = 0.f;

    #pragma unroll 1
    for (int jt = 0; jt < LSEQ / 64; jt++) {
        __syncthreads();   // prior PV reads of Ps/Vs done; Ks/Ms reuse safe
        // Load K, V (cvt tf32), mask tiles
        #pragma unroll
        for (int i = 0; i < 8; i++) {
            int s = tid + 128 * i;
            int r = s >> 4, c = (s & 15) * 4;
            float4 k4 = *(const float4*)&kp[(size_t)(jt * 64 + r) * 64 + c];
            uint4 tk = { f2tf32(k4.x), f2tf32(k4.y), f2tf32(k4.z), f2tf32(k4.w) };
            *(uint4*)&Ks[r * 68 + c] = tk;
            float4 v4 = *(const float4*)&vp[(size_t)(jt * 64 + r) * 64 + c];
            uint4 tv = { f2tf32(v4.x), f2tf32(v4.y), f2tf32(v4.z), f2tf32(v4.w) };
            *(uint4*)&Vs[r * 72 + c] = tv;
            float4 m4 = *(const float4*)&mask[((size_t)bb * LSEQ + q0 + r) * LSEQ + jt * 64 + c];
            *(float4*)&Ms[r * 68 + c] = m4;
        }
        __syncthreads();

        // S = Q K^T (scaled)
        float sacc[8][4];
        #pragma unroll
        for (int j = 0; j < 8; j++)
            #pragma unroll
            for (int r = 0; r < 4; r++) sacc[j][r] = 0.f;
        #pragma unroll
        for (int kk = 0; kk < 8; kk++) {
            #pragma unroll
            for (int j = 0; j < 8; j++) {
                uint32_t bf[2];
                bf[0] = Ks[(j * 8 + g) * 68 + kk * 8 + t];
                bf[1] = Ks[(j * 8 + g) * 68 + kk * 8 + t + 4];
                mma8(sacc[j], qa[kk], bf);
            }
        }

        // exp, mask, accumulate sums, write P (tf32) to smem
        #pragma unroll
        for (int j = 0; j < 8; j++) {
            float p0 = __expf(sacc[j][0]);
            float p1 = __expf(sacc[j][1]);
            float p2 = __expf(sacc[j][2]);
            float p3 = __expf(sacc[j][3]);
            float2 mlo = *(const float2*)&Ms[(rw + g) * 68 + j * 8 + 2 * t];
            float2 mhi = *(const float2*)&Ms[(rw + g + 8) * 68 + j * 8 + 2 * t];
            float w0 = p0 * mlo.x, w1 = p1 * mlo.y;
            float w2 = p2 * mhi.x, w3 = p3 * mhi.y;
            sa_lo += p0 + p1;  sa_hi += p2 + p3;
            sk_lo += w0 + w1;  sk_hi += w2 + w3;
            uint2 plo = { f2tf32(w0), f2tf32(w1) };
            uint2 phi = { f2tf32(w2), f2tf32(w3) };
            *(uint2*)&Ps[(rw + g) * 68 + j * 8 + 2 * t] = plo;
            *(uint2*)&Ps[(rw + g + 8) * 68 + j * 8 + 2 * t] = phi;
        }
        __syncthreads();

        // zacc += P @ V
        #pragma unroll
        for (int kk = 0; kk < 8; kk++) {
            uint32_t pa[4];
            pa[0] = Ps[(rw + g) * 68 + kk * 8 + t];
            pa[1] = Ps[(rw + g + 8) * 68 + kk * 8 + t];
            pa[2] = Ps[(rw + g) * 68 + kk * 8 + t + 4];
            pa[3] = Ps[(rw + g + 8) * 68 + kk * 8 + t + 4];
            #pragma unroll
            for (int j = 0; j < 8; j++) {
                uint32_t bf[2];
                bf[0] = Vs[(kk * 8 + t) * 72 + j * 8 + g];
                bf[1] = Vs[(kk * 8 + t + 4) * 72 + j * 8 + g];
                mma8(zacc[j], pa, bf);
            }
        }
    }

    // Reduce row sums across the 4 lanes of each group (cols spread over t)
    #pragma unroll
    for (int d = 1; d <= 2; d <<= 1) {
        sa_lo += __shfl_xor_sync(0xffffffffu, sa_lo, d);
        sa_hi += __shfl_xor_sync(0xffffffffu, sa_hi, d);
        sk_lo += __shfl_xor_sync(0xffffffffu, sk_lo, d);
        sk_hi += __shfl_xor_sync(0xffffffffu, sk_hi, d);
    }
    float inv_lo = 1.f / (sk_lo + 1e-10f * sa_lo);
    float inv_hi = 1.f / (sk_hi + 1e-10f * sa_hi);

    // Write z[b, l, h*64 + dh]
    size_t row_lo = (size_t)bb * LSEQ + q0 + rw + g;
    size_t row_hi = row_lo + 8;
    #pragma unroll
    for (int j = 0; j < 8; j++) {
        int dh = hh * 64 + j * 8 + 2 * t;
        float2 o0 = { zacc[j][0] * inv_lo, zacc[j][1] * inv_lo };
        float2 o1 = { zacc[j][2] * inv_hi, zacc[j][3] * inv_hi };
        *(float2*)&z[row_lo * INNER + dh] = o0;
        *(float2*)&z[row_hi * INNER + dh] = o1;
    }
}

// ---------------------------------------------------------------------------
extern "C" void kernel_launch(void* const* d_in, const int* in_sizes, int n_in,
                              void* d_out, int out_size)
{
    const float* x     = (const float*)d_in[0];  // [2,2048,1024]
    const float* mask  = (const float*)d_in[1];  // [2,2048,2048]
    const float* W_qkv = (const float*)d_in[2];  // [1024,3072]
    const float* W_out = (const float*)d_in[3];  // [1024,1024]
    const float* b_out = (const float*)d_in[4];  // [1024]
    float* out = (float*)d_out;

    // Transpose weights to [n][k] for the col-major B operand
    {
        dim3 blk(32, 8);
        transpose32<<<dim3(3072 / 32, 1024 / 32), blk>>>(W_qkv, g_wqkvT, 1024, 3072);
        transpose32<<<dim3(1024 / 32, 1024 / 32), blk>>>(W_out, g_woutT, 1024, 1024);
    }

    const int gemm_smem = 2 * 128 * 68 * 4;   // 69632 B
    cudaFuncSetAttribute(mma_gemm, cudaFuncAttributeMaxDynamicSharedMemorySize, gemm_smem);

    // QKV projection -> scatter to q/k/v
    mma_gemm<<<dim3(3072 / 128, 4096 / 128), 256, gemm_smem>>>(
        x, g_wqkvT, nullptr, nullptr, 0);

    // Attention
    const int attn_smem = (64 * 68 * 3 + 64 * 72) * 4;  // 70656 B
    cudaFuncSetAttribute(attn_mma, cudaFuncAttributeMaxDynamicSharedMemorySize, attn_smem);
    attn_mma<<<dim3(LSEQ / 64, NB * NH), 128, attn_smem>>>(mask, g_z);

    // Output projection + bias
    mma_gemm<<<dim3(1024 / 128, 4096 / 128), 256, gemm_smem>>>(
        g_z, g_woutT, b_out, out, 1);
}